// round 14
// baseline (speedup 1.0000x reference)
#include <cuda_runtime.h>
#include <cuda_bf16.h>
#include <cstdint>

#define NPAIR 1024
#define NN 128
#define CC 64
#define NDIAG 255
#define SX 70                        // bf16 A/B staging row stride (halves)
#define DSD 132                      // diag-major smem stride (halves); row = 264B, 8B-aligned

#define INFV 1e30f
#define LOG2E 1.4426950408889634f
#define LN2f  0.6931471805599453f

// dyn smem: staging A[128*70]+B[128*70] bf16 = 35840B, aliased under diag-major D 255*132*2
#define SMEM_BYTES (NDIAG * DSD * 2 + 16)

__device__ float g_bl[NPAIR];
__device__ unsigned int g_done;      // zero-init; reset by the reducing block each run

__device__ __forceinline__ float ex2f(float x) {
    float r; asm("ex2.approx.ftz.f32 %0, %1;" : "=f"(r) : "f"(x)); return r;
}
__device__ __forceinline__ float lg2f(float x) {
    float r; asm("lg2.approx.ftz.f32 %0, %1;" : "=f"(r) : "f"(x)); return r;
}

__device__ __forceinline__ void mma_bf16(float c[4], uint32_t a0, uint32_t a1, uint32_t a2,
                                         uint32_t a3, uint32_t b0, uint32_t b1) {
    asm volatile(
        "mma.sync.aligned.m16n8k16.row.col.f32.bf16.bf16.f32 "
        "{%0,%1,%2,%3}, {%4,%5,%6,%7}, {%8,%9}, {%0,%1,%2,%3};"
        : "+f"(c[0]), "+f"(c[1]), "+f"(c[2]), "+f"(c[3])
        : "r"(a0), "r"(a1), "r"(a2), "r"(a3), "r"(b0), "r"(b1));
}

// one wavefront step; u packs D for rows 4t..4t+3 on diagonal d (4 bf16)
__device__ __forceinline__ void dp_step(int d, uint2 u, float r1[4], float r2[4],
                                        float& upB, float& dgB, int lane, int i_first) {
    float2 f01 = __bfloat1622float2(*(__nv_bfloat162*)&u.x);
    float2 f23 = __bfloat1622float2(*(__nv_bfloat162*)&u.y);
    float dv[4] = {f01.x, f01.y, f23.x, f23.y};

    float nw[4];
#pragma unroll
    for (int k = 0; k < 4; k++) {
        int i = i_first + k;
        int j = d - i;
        bool valid = (unsigned)j < (unsigned)NN;

        float up = (k == 0) ? upB : r1[k - 1];
        float dg = (k == 0) ? dgB : r2[k - 1];
        float lf = r1[k];

        float mn = fminf(lf, fminf(up, dg));
        float mx = fmaxf(lf, fmaxf(up, dg));
        float md = fmaxf(fminf(lf, up), fminf(fmaxf(lf, up), dg));
        float s  = 1.f + ex2f(mn - md) + ex2f(mn - mx);
        float r  = dv[k] + mn - lg2f(s);
        nw[k] = valid ? r : INFV;
    }

    float newUp = __shfl_up_sync(0xffffffffu, nw[3], 1);   // dgB(d+1) == upB(d)
    dgB = upB;
    upB = (lane == 0) ? INFV : newUp;

#pragma unroll
    for (int k = 0; k < 4; k++) { r2[k] = r1[k]; r1[k] = nw[k]; }
}

// ---------------- Fused: HMMA GEMM -> diag-major smem D -> in-smem warp DP ----------
__global__ void __launch_bounds__(256, 2) dtw_fused_kernel(const float* __restrict__ x,
                                                           const float* __restrict__ y,
                                                           float* __restrict__ out) {
    extern __shared__ __nv_bfloat16 smh[];   // staging (phase1) aliased under diag-major D
    __shared__ float sx2[NN];
    __shared__ float sy2[NN];

    __nv_bfloat16* xs = smh;                 // [128][SX]
    __nv_bfloat16* ys = smh + NN * SX;       // [128][SX]

    const int p    = blockIdx.x;
    const int tid  = threadIdx.x;
    const int wid  = tid >> 5;
    const int lane = tid & 31;
    const int m0   = wid * 16;

    const float* __restrict__ xb = x + (size_t)p * NN * CC;
    const float* __restrict__ yb = y + (size_t)p * NN * CC;

    // load fp32 -> bf16 smem; fused row sum-of-squares
    for (int r = m0; r < m0 + 16; r++) {
        float2 vx = *(const float2*)&xb[r * CC + lane * 2];
        float2 vy = *(const float2*)&yb[r * CC + lane * 2];
        __nv_bfloat162 hx = __floats2bfloat162_rn(vx.x, vx.y);
        __nv_bfloat162 hy = __floats2bfloat162_rn(vy.x, vy.y);
        *(uint32_t*)&xs[r * SX + lane * 2] = *(uint32_t*)&hx;
        *(uint32_t*)&ys[r * SX + lane * 2] = *(uint32_t*)&hy;
        float sxq = vx.x * vx.x + vx.y * vx.y;
        float syq = vy.x * vy.x + vy.y * vy.y;
#pragma unroll
        for (int o = 16; o > 0; o >>= 1) {
            sxq += __shfl_xor_sync(0xffffffffu, sxq, o);
            syq += __shfl_xor_sync(0xffffffffu, syq, o);
        }
        if (lane == 0) { sx2[r] = sxq; sy2[r] = syq; }
    }
    __syncthreads();

    const int frow = lane >> 2;
    const int fk   = (lane & 3) * 2;

    uint32_t a[4][4];
#pragma unroll
    for (int k = 0; k < 4; k++) {
        int kb = k * 16 + fk;
        a[k][0] = *(uint32_t*)&xs[(m0 + frow)     * SX + kb];
        a[k][1] = *(uint32_t*)&xs[(m0 + frow + 8) * SX + kb];
        a[k][2] = *(uint32_t*)&xs[(m0 + frow)     * SX + kb + 8];
        a[k][3] = *(uint32_t*)&xs[(m0 + frow + 8) * SX + kb + 8];
    }

    float acc[16][4];
#pragma unroll
    for (int nt = 0; nt < 16; nt++) {
        acc[nt][0] = acc[nt][1] = acc[nt][2] = acc[nt][3] = 0.f;
        const int nrow = nt * 8 + frow;
#pragma unroll
        for (int k = 0; k < 4; k++) {
            int kb = k * 16 + fk;
            uint32_t b0 = *(uint32_t*)&ys[nrow * SX + kb];
            uint32_t b1 = *(uint32_t*)&ys[nrow * SX + kb + 8];
            mma_bf16(acc[nt], a[k][0], a[k][1], a[k][2], a[k][3], b0, b1);
        }
    }
    __syncthreads();                     // GEMM smem reads done; alias as diag-major D

    // epilogue: C frags straight into diag-major smem S[(i+j)*DSD + i]
    const int ccol = (lane & 3) * 2;
    const int r0 = m0 + frow;
    const float xx0 = sx2[r0], xx1 = sx2[r0 + 8];
#pragma unroll
    for (int nt = 0; nt < 16; nt++) {
        int n0 = nt * 8 + ccol;
        float yy0 = sy2[n0], yy1 = sy2[n0 + 1];
        float d00 = (xx0 + yy0 - 2.f * acc[nt][0]) * LOG2E;
        float d01 = (xx0 + yy1 - 2.f * acc[nt][1]) * LOG2E;
        float d10 = (xx1 + yy0 - 2.f * acc[nt][2]) * LOG2E;
        float d11 = (xx1 + yy1 - 2.f * acc[nt][3]) * LOG2E;
        int db = r0 + n0;
        smh[(db)     * DSD + r0]     = __float2bfloat16(d00);
        smh[(db + 1) * DSD + r0]     = __float2bfloat16(d01);
        smh[(db + 8) * DSD + r0 + 8] = __float2bfloat16(d10);
        smh[(db + 9) * DSD + r0 + 8] = __float2bfloat16(d11);
    }
    __syncthreads();

    if (wid != 0) return;                // warps 1..7 done; warp 0 runs the DP in-smem

    // ---- warp-synchronous DP on smem D; LDS.64 per lane per diagonal ----
    const uint2* __restrict__ S2 = (const uint2*)smh;   // row stride DSD/4 = 33 uint2
    float r1[4], r2[4];
#pragma unroll
    for (int k = 0; k < 4; k++) { r1[k] = INFV; r2[k] = INFV; }

    const int i_first = 4 * lane;
    float upB = INFV;
    float dgB = (lane == 0) ? 0.f : INFV;

    uint2 pf0 = S2[0 * 33 + lane];
    uint2 pf1 = S2[1 * 33 + lane];
    uint2 pf2 = S2[2 * 33 + lane];
    uint2 pf3 = S2[3 * 33 + lane];

#pragma unroll 1
    for (int d = 0; d < 252; d += 4) {
        dp_step(d + 0, pf0, r1, r2, upB, dgB, lane, i_first);
        pf0 = S2[min(d + 4, NDIAG - 1) * 33 + lane];
        dp_step(d + 1, pf1, r1, r2, upB, dgB, lane, i_first);
        pf1 = S2[min(d + 5, NDIAG - 1) * 33 + lane];
        dp_step(d + 2, pf2, r1, r2, upB, dgB, lane, i_first);
        pf2 = S2[min(d + 6, NDIAG - 1) * 33 + lane];
        dp_step(d + 3, pf3, r1, r2, upB, dgB, lane, i_first);
        pf3 = S2[min(d + 7, NDIAG - 1) * 33 + lane];
    }
    dp_step(252, pf0, r1, r2, upB, dgB, lane, i_first);
    dp_step(253, pf1, r1, r2, upB, dgB, lane, i_first);
    dp_step(254, pf2, r1, r2, upB, dgB, lane, i_first);

    int last;
    if (lane == 31) {
        g_bl[p] = r1[3] * LN2f;          // R[127][127] in nat-log units
        __threadfence();
        unsigned int old = atomicAdd(&g_done, 1u);
        last = (old == NPAIR - 1) ? 1 : 0;
    }
    last = __shfl_sync(0xffffffffu, last, 31);

    // ---- folded deterministic reduction: exactly one (the last) CTA reduces ----
    if (last) {
        __threadfence();
        float s = 0.f;
#pragma unroll
        for (int k = 0; k < 32; k++) s += g_bl[lane * 32 + k];
        out[lane] = s;
        __syncwarp();
        if (lane == 0) g_done = 0;       // reset for next graph replay
    }
}

extern "C" void kernel_launch(void* const* d_in, const int* in_sizes, int n_in,
                              void* d_out, int out_size) {
    (void)in_sizes; (void)n_in; (void)out_size;
    const float* x  = (const float*)d_in[0];
    const float* xr = (const float*)d_in[1];
    cudaFuncSetAttribute(dtw_fused_kernel, cudaFuncAttributeMaxDynamicSharedMemorySize, SMEM_BYTES);
    dtw_fused_kernel<<<NPAIR, 256, SMEM_BYTES>>>(x, xr, (float*)d_out);
}

// round 17
// speedup vs baseline: 1.2261x; 1.2261x over previous
#include <cuda_runtime.h>
#include <cuda_bf16.h>
#include <cstdint>

#define NPAIR 1024
#define NN 128
#define CC 64
#define NDIAG 255
#define SX 70                        // bf16 A/B smem row stride (halves)
#define DSD 130                      // diag-major smem stride (halves, even for u32 reads)

#define INFV 1e30f
#define LOG2E 1.4426950408889634f
#define LN2f  0.6931471805599453f

// dyn smem: phase1 A[128*70]+B[128*70] bf16 = 35840B; phase2 diag-major D 255*130*2=66300B
#define SMEM_BYTES (NDIAG * DSD * 2 + 8)

// diag-major bf16 D: g_D[p*NDIAG*NN + d*NN + i] = D[i][d-i], pre-scaled by log2(e)
// 128B-aligned so 32B v8 stores are legal at every group
__device__ __align__(128) __nv_bfloat16 g_D[(size_t)NPAIR * NDIAG * NN];
__device__ float g_bl[NPAIR];
__device__ unsigned int g_done;      // zero-initialized; reset by the reducing block

__device__ __forceinline__ float ex2f(float x) {
    float r; asm("ex2.approx.ftz.f32 %0, %1;" : "=f"(r) : "f"(x)); return r;
}
__device__ __forceinline__ float lg2f(float x) {
    float r; asm("lg2.approx.ftz.f32 %0, %1;" : "=f"(r) : "f"(x)); return r;
}

// 32B pinned store (evict_last) — only legal width for L2 policy hints here
__device__ __forceinline__ void stg_el_v8(unsigned int* p, const unsigned int v[8]) {
    asm volatile("st.global.L2::evict_last.v8.b32 [%0], {%1,%2,%3,%4,%5,%6,%7,%8};"
                 :: "l"(p), "r"(v[0]), "r"(v[1]), "r"(v[2]), "r"(v[3]),
                    "r"(v[4]), "r"(v[5]), "r"(v[6]), "r"(v[7]) : "memory");
}

__device__ __forceinline__ void mma_bf16(float c[4], uint32_t a0, uint32_t a1, uint32_t a2,
                                         uint32_t a3, uint32_t b0, uint32_t b1) {
    asm volatile(
        "mma.sync.aligned.m16n8k16.row.col.f32.bf16.bf16.f32 "
        "{%0,%1,%2,%3}, {%4,%5,%6,%7}, {%8,%9}, {%0,%1,%2,%3};"
        : "+f"(c[0]), "+f"(c[1]), "+f"(c[2]), "+f"(c[3])
        : "r"(a0), "r"(a1), "r"(a2), "r"(a3), "r"(b0), "r"(b1));
}

// ---------------- Phase A: HMMA bf16 GEMM -> diag-major smem -> pinned store ---------
__global__ void __launch_bounds__(256, 2) dtw_cost_kernel(const float* __restrict__ x,
                                                          const float* __restrict__ y) {
    extern __shared__ __nv_bfloat16 smh[];        // phase1: xs/ys; phase2: diag-major D
    __shared__ float sx2[NN];
    __shared__ float sy2[NN];

    __nv_bfloat16* xs = smh;
    __nv_bfloat16* ys = smh + NN * SX;

    const int p    = blockIdx.x;
    const int tid  = threadIdx.x;
    const int wid  = tid >> 5;
    const int lane = tid & 31;
    const int m0   = wid * 16;

    const float* __restrict__ xb = x + (size_t)p * NN * CC;
    const float* __restrict__ yb = y + (size_t)p * NN * CC;

    // load fp32 -> bf16 smem; fused row sum-of-squares
    for (int r = m0; r < m0 + 16; r++) {
        float2 vx = *(const float2*)&xb[r * CC + lane * 2];
        float2 vy = *(const float2*)&yb[r * CC + lane * 2];
        __nv_bfloat162 hx = __floats2bfloat162_rn(vx.x, vx.y);
        __nv_bfloat162 hy = __floats2bfloat162_rn(vy.x, vy.y);
        *(uint32_t*)&xs[r * SX + lane * 2] = *(uint32_t*)&hx;
        *(uint32_t*)&ys[r * SX + lane * 2] = *(uint32_t*)&hy;
        float sxq = vx.x * vx.x + vx.y * vx.y;
        float syq = vy.x * vy.x + vy.y * vy.y;
#pragma unroll
        for (int o = 16; o > 0; o >>= 1) {
            sxq += __shfl_xor_sync(0xffffffffu, sxq, o);
            syq += __shfl_xor_sync(0xffffffffu, syq, o);
        }
        if (lane == 0) { sx2[r] = sxq; sy2[r] = syq; }
    }
    __syncthreads();

    const int frow = lane >> 2;          // 0..7
    const int fk   = (lane & 3) * 2;     // 0,2,4,6

    uint32_t a[4][4];
#pragma unroll
    for (int k = 0; k < 4; k++) {
        int kb = k * 16 + fk;
        a[k][0] = *(uint32_t*)&xs[(m0 + frow)     * SX + kb];
        a[k][1] = *(uint32_t*)&xs[(m0 + frow + 8) * SX + kb];
        a[k][2] = *(uint32_t*)&xs[(m0 + frow)     * SX + kb + 8];
        a[k][3] = *(uint32_t*)&xs[(m0 + frow + 8) * SX + kb + 8];
    }

    float acc[16][4];
#pragma unroll
    for (int nt = 0; nt < 16; nt++) {
        acc[nt][0] = acc[nt][1] = acc[nt][2] = acc[nt][3] = 0.f;
        const int nrow = nt * 8 + frow;
#pragma unroll
        for (int k = 0; k < 4; k++) {
            int kb = k * 16 + fk;
            uint32_t b0 = *(uint32_t*)&ys[nrow * SX + kb];
            uint32_t b1 = *(uint32_t*)&ys[nrow * SX + kb + 8];
            mma_bf16(acc[nt], a[k][0], a[k][1], a[k][2], a[k][3], b0, b1);
        }
    }
    __syncthreads();                     // GEMM smem reads done; alias as diag-major D

    // epilogue: C frags straight into diag-major smem S[(i+j)*DSD + i]
    const int ccol = (lane & 3) * 2;
    const int r0 = m0 + frow;
    const float xx0 = sx2[r0], xx1 = sx2[r0 + 8];
#pragma unroll
    for (int nt = 0; nt < 16; nt++) {
        int n0 = nt * 8 + ccol;
        float yy0 = sy2[n0], yy1 = sy2[n0 + 1];
        float d00 = (xx0 + yy0 - 2.f * acc[nt][0]) * LOG2E;
        float d01 = (xx0 + yy1 - 2.f * acc[nt][1]) * LOG2E;
        float d10 = (xx1 + yy0 - 2.f * acc[nt][2]) * LOG2E;
        float d11 = (xx1 + yy1 - 2.f * acc[nt][3]) * LOG2E;
        int db = r0 + n0;
        smh[(db)     * DSD + r0]     = __float2bfloat16(d00);
        smh[(db + 1) * DSD + r0]     = __float2bfloat16(d01);
        smh[(db + 8) * DSD + r0 + 8] = __float2bfloat16(d10);
        smh[(db + 9) * DSD + r0 + 8] = __float2bfloat16(d11);
    }
    __syncthreads();

    // restage: smem(diag-major) -> global(diag-major), 32B pinned stores
    // group g (32B = 8 u32): d = g>>3, ip0 = (g&7)*8 ; 2040 groups per pair
    const uint32_t* __restrict__ S32 = (const uint32_t*)smh;   // u32 idx = d*(DSD/2)+ip
    unsigned int* __restrict__ outD = (unsigned int*)(g_D + (size_t)p * NDIAG * NN);
    for (int g = tid; g < NDIAG * 8; g += 256) {
        int d   = g >> 3;
        int ip0 = (g & 7) * 8;
        unsigned int v[8];
#pragma unroll
        for (int q = 0; q < 8; q++) v[q] = S32[d * (DSD / 2) + ip0 + q];
        stg_el_v8(&outD[g * 8], v);
    }
}

// ---------------- Phase B: warp-per-pair DP, depth-8 register prefetch ----------------
__device__ __forceinline__ void dp_step(int d, uint2 u, float r1[4], float r2[4],
                                        float& upB, float& dgB, int lane, int i_first) {
    float2 f01 = __bfloat1622float2(*(__nv_bfloat162*)&u.x);
    float2 f23 = __bfloat1622float2(*(__nv_bfloat162*)&u.y);
    float dv[4] = {f01.x, f01.y, f23.x, f23.y};

    float nw[4];
#pragma unroll
    for (int k = 0; k < 4; k++) {
        int i = i_first + k;
        int j = d - i;
        bool valid = (unsigned)j < (unsigned)NN;

        float up = (k == 0) ? upB : r1[k - 1];
        float dg = (k == 0) ? dgB : r2[k - 1];
        float lf = r1[k];

        float mn = fminf(lf, fminf(up, dg));
        float mx = fmaxf(lf, fmaxf(up, dg));
        float md = fmaxf(fminf(lf, up), fminf(fmaxf(lf, up), dg));
        float s  = 1.f + ex2f(mn - md) + ex2f(mn - mx);
        float r  = dv[k] + mn - lg2f(s);
        nw[k] = valid ? r : INFV;
    }

    // dgB(d+1) == upB(d); one shfl per diagonal
    float newUp = __shfl_up_sync(0xffffffffu, nw[3], 1);
    dgB = upB;
    upB = (lane == 0) ? INFV : newUp;

#pragma unroll
    for (int k = 0; k < 4; k++) { r2[k] = r1[k]; r1[k] = nw[k]; }
}

__global__ void __launch_bounds__(32) dtw_dp_kernel(float* __restrict__ out) {
    __shared__ int s_last;
    const int p    = blockIdx.x;
    const int lane = threadIdx.x;
    const uint2* __restrict__ Dp = (const uint2*)(g_D + (size_t)p * NDIAG * NN);

    float r1[4], r2[4];
#pragma unroll
    for (int k = 0; k < 4; k++) { r1[k] = INFV; r2[k] = INFV; }

    const int i_first = 4 * lane;
    float upB = INFV;
    float dgB = (lane == 0) ? 0.f : INFV;

    // named-register prefetch ring, depth 8
    uint2 pf0 = Dp[0 * 32 + lane];
    uint2 pf1 = Dp[1 * 32 + lane];
    uint2 pf2 = Dp[2 * 32 + lane];
    uint2 pf3 = Dp[3 * 32 + lane];
    uint2 pf4 = Dp[4 * 32 + lane];
    uint2 pf5 = Dp[5 * 32 + lane];
    uint2 pf6 = Dp[6 * 32 + lane];
    uint2 pf7 = Dp[7 * 32 + lane];

#pragma unroll 1
    for (int d = 0; d < 240; d += 8) {
        dp_step(d + 0, pf0, r1, r2, upB, dgB, lane, i_first); pf0 = Dp[(d +  8) * 32 + lane];
        dp_step(d + 1, pf1, r1, r2, upB, dgB, lane, i_first); pf1 = Dp[(d +  9) * 32 + lane];
        dp_step(d + 2, pf2, r1, r2, upB, dgB, lane, i_first); pf2 = Dp[(d + 10) * 32 + lane];
        dp_step(d + 3, pf3, r1, r2, upB, dgB, lane, i_first); pf3 = Dp[(d + 11) * 32 + lane];
        dp_step(d + 4, pf4, r1, r2, upB, dgB, lane, i_first); pf4 = Dp[(d + 12) * 32 + lane];
        dp_step(d + 5, pf5, r1, r2, upB, dgB, lane, i_first); pf5 = Dp[(d + 13) * 32 + lane];
        dp_step(d + 6, pf6, r1, r2, upB, dgB, lane, i_first); pf6 = Dp[(d + 14) * 32 + lane];
        dp_step(d + 7, pf7, r1, r2, upB, dgB, lane, i_first); pf7 = Dp[(d + 15) * 32 + lane];
    }
    // tail: pf0..pf7 hold diagonals 240..247
    dp_step(240, pf0, r1, r2, upB, dgB, lane, i_first); pf0 = Dp[248 * 32 + lane];
    dp_step(241, pf1, r1, r2, upB, dgB, lane, i_first); pf1 = Dp[249 * 32 + lane];
    dp_step(242, pf2, r1, r2, upB, dgB, lane, i_first); pf2 = Dp[250 * 32 + lane];
    dp_step(243, pf3, r1, r2, upB, dgB, lane, i_first); pf3 = Dp[251 * 32 + lane];
    dp_step(244, pf4, r1, r2, upB, dgB, lane, i_first); pf4 = Dp[252 * 32 + lane];
    dp_step(245, pf5, r1, r2, upB, dgB, lane, i_first); pf5 = Dp[253 * 32 + lane];
    dp_step(246, pf6, r1, r2, upB, dgB, lane, i_first); pf6 = Dp[254 * 32 + lane];
    dp_step(247, pf7, r1, r2, upB, dgB, lane, i_first);
    dp_step(248, pf0, r1, r2, upB, dgB, lane, i_first);
    dp_step(249, pf1, r1, r2, upB, dgB, lane, i_first);
    dp_step(250, pf2, r1, r2, upB, dgB, lane, i_first);
    dp_step(251, pf3, r1, r2, upB, dgB, lane, i_first);
    dp_step(252, pf4, r1, r2, upB, dgB, lane, i_first);
    dp_step(253, pf5, r1, r2, upB, dgB, lane, i_first);
    dp_step(254, pf6, r1, r2, upB, dgB, lane, i_first);

    if (lane == 31) g_bl[p] = r1[3] * LN2f;

    // ---- folded deterministic reduction: exactly one (the last) block reduces ----
    if (lane == 0) {
        __threadfence();
        unsigned int old = atomicAdd(&g_done, 1u);
        s_last = (old == NPAIR - 1) ? 1 : 0;
    }
    __syncwarp();
    if (s_last) {
        __threadfence();
        int b = lane;
        float s = 0.f;
#pragma unroll
        for (int k = 0; k < 32; k++) s += g_bl[b * 32 + k];
        out[b] = s;
        __syncwarp();
        if (lane == 0) g_done = 0;   // reset for next graph replay
    }
}

extern "C" void kernel_launch(void* const* d_in, const int* in_sizes, int n_in,
                              void* d_out, int out_size) {
    (void)in_sizes; (void)n_in; (void)out_size;
    const float* x  = (const float*)d_in[0];
    const float* xr = (const float*)d_in[1];
    cudaFuncSetAttribute(dtw_cost_kernel, cudaFuncAttributeMaxDynamicSharedMemorySize, SMEM_BYTES);
    dtw_cost_kernel<<<NPAIR, 256, SMEM_BYTES>>>(x, xr);
    dtw_dp_kernel<<<NPAIR, 32>>>((float*)d_out);
}